// round 12
// baseline (speedup 1.0000x reference)
#include <cuda_runtime.h>
#include <cuda_fp16.h>
#include <cstdint>
#include <cstddef>

// ---------------------------------------------------------------------------
// Problem constants
// ---------------------------------------------------------------------------
constexpr int N_ATOMS  = 100000;
constexpr int N_BONDS  = 200001;
constexpr int ATOM_FDIM = 39;
constexpr int IN_FDIM   = 50;
constexpr int OUT_FDIM  = 295;
constexpr int MAX_NB    = 6;
constexpr int HIDDEN    = 256;
constexpr int N_MOLS    = 2000;
constexpr int APM       = 50;

constexpr int KP0 = 64;    // init K (50 -> 64)
constexpr int KP1 = 256;   // rounds K
constexpr int KP2 = 320;   // readout K: [nei(256) | fatoms(39) | pad]
constexpr int BK  = 16;    // one m16n8k16 step per chunk
constexpr int BM  = 64;    // M tile
constexpr int THREADS = 512;   // 16 warps; 2 CTAs/SM -> 50% occupancy

// ---------------------------------------------------------------------------
// Scratch (fp16 everywhere except final pool output)
// ---------------------------------------------------------------------------
__device__ __align__(16) __half g_binput[(size_t)N_BONDS * HIDDEN];
__device__ __align__(16) __half g_msg0  [(size_t)N_BONDS * HIDDEN];
__device__ __align__(16) __half g_msg1  [(size_t)N_BONDS * HIDDEN];
__device__ __align__(16) __half g_atomh [(size_t)N_ATOMS * HIDDEN];
__device__ __align__(16) __half g_fbpad [(size_t)N_BONDS * KP0];
__device__ __align__(16) __half g_afeat [(size_t)N_ATOMS * 64];
__device__ __align__(16) __half g_Wi    [(size_t)HIDDEN * KP0];   // [n][k]
__device__ __align__(16) __half g_Wh    [(size_t)HIDDEN * KP1];   // [n][k]
__device__ __align__(16) __half g_Wo    [(size_t)HIDDEN * KP2];   // [n][k], cols reordered

// ---------------------------------------------------------------------------
// Helpers
// ---------------------------------------------------------------------------
__device__ __forceinline__ uint32_t smem_u32(const void* p) {
    uint32_t a;
    asm("{ .reg .u64 t; cvta.to.shared.u64 t, %1; cvt.u32.u64 %0, t; }" : "=r"(a) : "l"(p));
    return a;
}
__device__ __forceinline__ void cp16(uint32_t dst, const void* src, uint32_t sz) {
    asm volatile("cp.async.ca.shared.global [%0], [%1], 16, %2;" :: "r"(dst), "l"(src), "r"(sz) : "memory");
}
__device__ __forceinline__ void cp_commit() {
    asm volatile("cp.async.commit_group;" ::: "memory");
}
template <int N>
__device__ __forceinline__ void cp_wait() {
    asm volatile("cp.async.wait_group %0;" :: "n"(N) : "memory");
}
// fp16 inputs, fp32 accumulate
__device__ __forceinline__ void mma16(float& d0, float& d1, float& d2, float& d3,
                                      uint32_t a0, uint32_t a1, uint32_t a2, uint32_t a3,
                                      uint32_t b0, uint32_t b1) {
    asm volatile(
        "mma.sync.aligned.m16n8k16.row.col.f32.f16.f16.f32 "
        "{%0,%1,%2,%3}, {%4,%5,%6,%7}, {%8,%9}, {%0,%1,%2,%3};"
        : "+f"(d0), "+f"(d1), "+f"(d2), "+f"(d3)
        : "r"(a0), "r"(a1), "r"(a2), "r"(a3), "r"(b0), "r"(b1));
}

// SMEM layout (bytes), 3-stage ring, BM=64 tiles
constexpr int GOFF_B  = 0;                        // 64 rows x 6 ints = 1536
constexpr int AOFF_B  = 1536;
constexpr int A_BUF_B = BM * 24 * 2;              // 3072
constexpr int BOFF_B  = AOFF_B + 3 * A_BUF_B;     // 10752
constexpr int B_BUF_B = 256 * 24 * 2;             // 12288
constexpr int SMEM_BYTES = BOFF_B + 3 * B_BUF_B;  // 47616

// ---------------------------------------------------------------------------
// Fused gather + fp16 HMMA GEMM. 512 threads, 16 warps as 2(M) x 8(N);
// warp tile 32x32 -> 32 acc regs/thread -> 2 CTAs/SM (50% occupancy).
// Gather executes at staging time (no register prefetch) — latency hidden
// across 32 warps/SM instead of intra-warp ILP.
// MODE 0: C2h <- raw fp16, Ch <- relu fp16     (init; no gather)
// MODE 1: Ch <- relu(binput + raw) fp16        (rounds; all chunks gathered)
// MODE 2: Ch <- relu(raw + b_o[n]) fp16        (readout; chunks <16 gathered)
// ---------------------------------------------------------------------------
template <int MODE, int KT>
__global__ void __launch_bounds__(THREADS, 2)
gemm_fused(const __half* __restrict__ msg,
           const int* __restrict__ graph,
           const __half* __restrict__ Apad, int ldah,
           const __half* __restrict__ Bt, int ldbh,
           const void* __restrict__ extra,
           __half* __restrict__ Ch,
           __half* __restrict__ C2h, int M) {
    extern __shared__ char smc[];
    int* sgidx = (int*)(smc + GOFF_B);
    const uint32_t sbase = smem_u32(smc);
    const int tid  = threadIdx.x;
    const int wid  = tid >> 5;
    const int lane = tid & 31;
    const int mBase = blockIdx.x * BM;
    const int warpM = (wid >> 3) * 32;   // 0 or 32
    const int warpN = (wid & 7) * 32;    // 0..224

    constexpr int FEAT0 = (MODE == 2) ? 16 : 0;
    auto gathered = [](int s) { return MODE == 1 || (MODE == 2 && s < 16); };

    const int grow  = tid >> 3;   // 0..63 (gather row)
    const int gslot = tid & 7;    // 2-half slot within 16-col chunk

    if (MODE != 0) {
        for (int i = tid; i < BM * MAX_NB; i += THREADS) {
            int gi = mBase * MAX_NB + i;
            sgidx[i] = (gi < M * MAX_NB) ? graph[gi] : 0;
        }
        __syncthreads();
    }
    const char* msgc = (const char*)msg;

    // direct gather: load 6 neighbor half2's, sum fp32, store to A tile
    auto store_gather = [&](int s) {
        float f0 = 0.f, f1 = 0.f;
#pragma unroll
        for (int j = 0; j < 6; ++j) {
            uint32_t idx = (uint32_t)sgidx[grow * 6 + j];
            uint32_t v = __ldg((const uint32_t*)(msgc + (size_t)idx * (HIDDEN * 2)
                                                 + s * (BK * 2) + gslot * 4));
            float2 e = __half22float2(*(const __half2*)&v);
            f0 += e.x; f1 += e.y;
        }
        uint32_t r;
        *(__half2*)&r = __floats2half2_rn(f0, f1);
        *(uint32_t*)(smc + AOFF_B + (s % 3) * A_BUF_B + (grow * 24 + gslot * 2) * 2) = r;
    };
    auto cpA = [&](int s) {
        if (tid < 128) {
            int row = tid >> 1, h = tid & 1;
            int gm = mBase + row;
            const void* src = Apad + (size_t)gm * ldah + (s - FEAT0) * BK + h * 8;
            uint32_t dst = sbase + AOFF_B + (s % 3) * A_BUF_B + (row * 24 + h * 8) * 2;
            cp16(dst, src, (gm < M) ? 16u : 0u);
        }
    };
    auto cpB = [&](int s) {
        int row = tid >> 1, h = tid & 1;   // 512 threads -> 256 rows x 2
        const void* src = Bt + (size_t)row * ldbh + s * BK + h * 8;
        uint32_t dst = sbase + BOFF_B + (s % 3) * B_BUF_B + (row * 24 + h * 8) * 2;
        cp16(dst, src, 16u);
    };

    // --- prologue: chunks 0 and 1 staged ---
    if (gathered(0)) store_gather(0); else cpA(0);
    cpB(0); cp_commit();
    if (KT > 1) {
        if (gathered(1)) store_gather(1); else cpA(1);
        cpB(1); cp_commit();
    }
    cp_wait<1>();
    __syncthreads();

    float acc[2][4][4];
#pragma unroll
    for (int a = 0; a < 2; ++a)
#pragma unroll
        for (int b = 0; b < 4; ++b)
#pragma unroll
            for (int c = 0; c < 4; ++c) acc[a][b][c] = 0.0f;

#pragma unroll 1
    for (int s = 0; s < KT; ++s) {
        const __half* bA = (const __half*)(smc + AOFF_B + (s % 3) * A_BUF_B);
        const __half* bB = (const __half*)(smc + BOFF_B + (s % 3) * B_BUF_B);
        const int k0 = (lane & 3) * 2;

        uint32_t afr[2][4];
#pragma unroll
        for (int mt = 0; mt < 2; ++mt) {
            const int r0 = warpM + mt * 16 + (lane >> 2);
            const int r1 = r0 + 8;
            afr[mt][0] = *(const uint32_t*)&bA[r0 * 24 + k0];
            afr[mt][1] = *(const uint32_t*)&bA[r1 * 24 + k0];
            afr[mt][2] = *(const uint32_t*)&bA[r0 * 24 + k0 + 8];
            afr[mt][3] = *(const uint32_t*)&bA[r1 * 24 + k0 + 8];
        }
#pragma unroll
        for (int nt = 0; nt < 4; ++nt) {
            const int nn = warpN + nt * 8 + (lane >> 2);
            uint32_t b0 = *(const uint32_t*)&bB[nn * 24 + k0];
            uint32_t b1 = *(const uint32_t*)&bB[nn * 24 + k0 + 8];
#pragma unroll
            for (int mt = 0; mt < 2; ++mt)
                mma16(acc[mt][nt][0], acc[mt][nt][1], acc[mt][nt][2], acc[mt][nt][3],
                      afr[mt][0], afr[mt][1], afr[mt][2], afr[mt][3], b0, b1);
        }

        // stage s+1 gather (buf (s+1)%3) and s+2 cp.async (buf (s+2)%3)
        if (s + 1 < KT && gathered(s + 1)) store_gather(s + 1);
        if (s + 2 < KT) {
            if (!gathered(s + 2)) cpA(s + 2);
            cpB(s + 2);
        }
        cp_commit();
        cp_wait<1>();
        __syncthreads();
    }

    // --- epilogue ---
#pragma unroll
    for (int mt = 0; mt < 2; ++mt) {
#pragma unroll
        for (int rg = 0; rg < 2; ++rg) {
            const int r = mBase + warpM + mt * 16 + (lane >> 2) + rg * 8;
            if (r < M) {
#pragma unroll
                for (int nt = 0; nt < 4; ++nt) {
                    const int col = warpN + nt * 8 + (lane & 3) * 2;
                    const size_t off = (size_t)r * HIDDEN + col;
                    float v0 = acc[mt][nt][rg * 2 + 0];
                    float v1 = acc[mt][nt][rg * 2 + 1];
                    if (MODE == 1) {
                        float2 ef = __half22float2(*(const __half2*)((const __half*)extra + off));
                        v0 += ef.x; v1 += ef.y;
                    }
                    if (MODE == 2) {
                        const float* bo = (const float*)extra;
                        v0 += __ldg(bo + col);
                        v1 += __ldg(bo + col + 1);
                    }
                    if (MODE == 0)
                        *(__half2*)(C2h + off) = __floats2half2_rn(v0, v1);
                    v0 = fmaxf(v0, 0.0f); v1 = fmaxf(v1, 0.0f);
                    *(__half2*)(Ch + off) = __floats2half2_rn(v0, v1);
                }
            }
        }
    }
}

// ---------------------------------------------------------------------------
// Producers
// ---------------------------------------------------------------------------
__global__ void pad_fb_k(const float* __restrict__ in, __half* __restrict__ out) {
    size_t i = (size_t)blockIdx.x * blockDim.x + threadIdx.x;
    if (i >= (size_t)N_BONDS * KP0) return;
    int r = (int)(i / KP0), c = (int)(i % KP0);
    out[i] = (c < IN_FDIM) ? __float2half_rn(in[(size_t)r * IN_FDIM + c]) : __half(0.f);
}
__global__ void cv_wi_k(const float* __restrict__ W, __half* __restrict__ out) {
    int i = blockIdx.x * blockDim.x + threadIdx.x;
    if (i >= HIDDEN * KP0) return;
    int n = i / KP0, k = i % KP0;
    out[i] = (k < IN_FDIM) ? __float2half_rn(W[(size_t)n * IN_FDIM + k]) : __half(0.f);
}
__global__ void cv_wh_k(const float* __restrict__ W, __half* __restrict__ out) {
    int i = blockIdx.x * blockDim.x + threadIdx.x;
    if (i >= HIDDEN * KP1) return;
    out[i] = __float2half_rn(W[i]);
}
__global__ void cv_wo_k(const float* __restrict__ W, __half* __restrict__ out) {
    int i = blockIdx.x * blockDim.x + threadIdx.x;
    if (i >= HIDDEN * KP2) return;
    int n = i / KP2, k = i % KP2;
    float v = 0.0f;
    if (k < 256) v = W[(size_t)n * OUT_FDIM + ATOM_FDIM + k];
    else if (k < OUT_FDIM) v = W[(size_t)n * OUT_FDIM + (k - 256)];
    out[i] = __float2half_rn(v);
}
__global__ void pad_afeat_k(const float* __restrict__ fatoms, __half* __restrict__ afeat) {
    int i = blockIdx.x * blockDim.x + threadIdx.x;
    if (i >= N_ATOMS * 64) return;
    int r = i / 64, c = i % 64;
    afeat[i] = (c < ATOM_FDIM) ? __float2half_rn(fatoms[(size_t)r * ATOM_FDIM + c]) : __half(0.f);
}

__global__ void pool_k(const __half* __restrict__ atomh, float* __restrict__ out) {
    const int mol = blockIdx.x;
    const int n   = threadIdx.x;
    const __half* base = atomh + (size_t)mol * APM * HIDDEN;
    float s = 0.0f;
#pragma unroll
    for (int i = 0; i < APM; ++i) s += __half2float(base[(size_t)i * HIDDEN + n]);
    out[(size_t)mol * HIDDEN + n] = s * (1.0f / (float)APM);
}

// ---------------------------------------------------------------------------
extern "C" void kernel_launch(void* const* d_in, const int* in_sizes, int n_in,
                              void* d_out, int out_size) {
    const float* fatoms = (const float*)d_in[0];
    const float* fbonds = (const float*)d_in[1];
    const int*   agraph = (const int*)  d_in[2];
    const int*   bgraph = (const int*)  d_in[3];
    const float* W_i = (const float*)d_in[5];
    const float* W_h = (const float*)d_in[6];
    const float* W_o = (const float*)d_in[7];
    const float* b_o = (const float*)d_in[8];
    float* out = (float*)d_out;

    __half *binput, *msg0, *msg1, *atomh, *fbpad, *afeat, *Wi, *Wh, *Wo;
    cudaGetSymbolAddress((void**)&binput, g_binput);
    cudaGetSymbolAddress((void**)&msg0,   g_msg0);
    cudaGetSymbolAddress((void**)&msg1,   g_msg1);
    cudaGetSymbolAddress((void**)&atomh,  g_atomh);
    cudaGetSymbolAddress((void**)&fbpad,  g_fbpad);
    cudaGetSymbolAddress((void**)&afeat,  g_afeat);
    cudaGetSymbolAddress((void**)&Wi,     g_Wi);
    cudaGetSymbolAddress((void**)&Wh,     g_Wh);
    cudaGetSymbolAddress((void**)&Wo,     g_Wo);

    cudaFuncSetAttribute(gemm_fused<0, KP0 / BK>, cudaFuncAttributeMaxDynamicSharedMemorySize, SMEM_BYTES);
    cudaFuncSetAttribute(gemm_fused<1, KP1 / BK>, cudaFuncAttributeMaxDynamicSharedMemorySize, SMEM_BYTES);
    cudaFuncSetAttribute(gemm_fused<2, KP2 / BK>, cudaFuncAttributeMaxDynamicSharedMemorySize, SMEM_BYTES);

    {
        size_t n = (size_t)N_BONDS * KP0;
        pad_fb_k<<<(unsigned)((n + 255) / 256), 256>>>(fbonds, fbpad);
        cv_wi_k<<<(HIDDEN * KP0 + 255) / 256, 256>>>(W_i, Wi);
        cv_wh_k<<<(HIDDEN * KP1 + 255) / 256, 256>>>(W_h, Wh);
        cv_wo_k<<<(HIDDEN * KP2 + 255) / 256, 256>>>(W_o, Wo);
        pad_afeat_k<<<(N_ATOMS * 64 + 255) / 256, 256>>>(fatoms, afeat);
    }

    const int tilesB = (N_BONDS + BM - 1) / BM;
    const int tilesA = (N_ATOMS + BM - 1) / BM;

    // init: binput(raw fp16) + msg0 = relu fp16
    gemm_fused<0, KP0 / BK><<<tilesB, THREADS, SMEM_BYTES>>>(
        nullptr, nullptr, fbpad, KP0, Wi, KP0,
        nullptr, msg0, binput, N_BONDS);

    // 5 message-passing rounds (gather fused)
    __half* cur = msg0;
    __half* nxt = msg1;
    for (int r = 0; r < 5; ++r) {
        gemm_fused<1, KP1 / BK><<<tilesB, THREADS, SMEM_BYTES>>>(
            cur, bgraph, nullptr, 0, Wh, KP1,
            binput, nxt, nullptr, N_BONDS);
        __half* t = cur; cur = nxt; nxt = t;
    }

    // atom readout (fp16 out)
    gemm_fused<2, KP2 / BK><<<tilesA, THREADS, SMEM_BYTES>>>(
        cur, agraph, afeat, 64, Wo, KP2,
        b_o, atomh, nullptr, N_ATOMS);

    // mean pool (fp32 accumulate)
    pool_k<<<N_MOLS, 256>>>(atomh, out);
}

// round 13
// speedup vs baseline: 1.7407x; 1.7407x over previous
#include <cuda_runtime.h>
#include <cuda_fp16.h>
#include <cstdint>
#include <cstddef>

// ---------------------------------------------------------------------------
// Problem constants
// ---------------------------------------------------------------------------
constexpr int N_ATOMS  = 100000;
constexpr int N_BONDS  = 200001;
constexpr int ATOM_FDIM = 39;
constexpr int IN_FDIM   = 50;
constexpr int OUT_FDIM  = 295;
constexpr int MAX_NB    = 6;
constexpr int HIDDEN    = 256;
constexpr int N_MOLS    = 2000;
constexpr int APM       = 50;

constexpr int KP0 = 64;    // init K (50 -> 64)
constexpr int KP1 = 256;   // rounds K
constexpr int KP2 = 320;   // readout K: [nei(256) | fatoms(39) | pad]
constexpr int BK  = 32;    // two m16n8k16 steps per chunk (half the barriers)
constexpr int BM  = 64;    // M tile (256 threads, 2 CTAs/SM) — R10 geometry

// ---------------------------------------------------------------------------
// Scratch (fp16 everywhere except final pool output)
// ---------------------------------------------------------------------------
__device__ __align__(16) __half g_binput[(size_t)N_BONDS * HIDDEN];
__device__ __align__(16) __half g_msg0  [(size_t)N_BONDS * HIDDEN];
__device__ __align__(16) __half g_msg1  [(size_t)N_BONDS * HIDDEN];
__device__ __align__(16) __half g_atomh [(size_t)N_ATOMS * HIDDEN];
__device__ __align__(16) __half g_fbpad [(size_t)N_BONDS * KP0];
__device__ __align__(16) __half g_afeat [(size_t)N_ATOMS * 64];
__device__ __align__(16) __half g_Wi    [(size_t)HIDDEN * KP0];   // [n][k]
__device__ __align__(16) __half g_Wh    [(size_t)HIDDEN * KP1];   // [n][k]
__device__ __align__(16) __half g_Wo    [(size_t)HIDDEN * KP2];   // [n][k], cols reordered

// ---------------------------------------------------------------------------
// Helpers
// ---------------------------------------------------------------------------
__device__ __forceinline__ uint32_t smem_u32(const void* p) {
    uint32_t a;
    asm("{ .reg .u64 t; cvta.to.shared.u64 t, %1; cvt.u32.u64 %0, t; }" : "=r"(a) : "l"(p));
    return a;
}
__device__ __forceinline__ void cp16(uint32_t dst, const void* src, uint32_t sz) {
    asm volatile("cp.async.ca.shared.global [%0], [%1], 16, %2;" :: "r"(dst), "l"(src), "r"(sz) : "memory");
}
__device__ __forceinline__ void cp_commit() {
    asm volatile("cp.async.commit_group;" ::: "memory");
}
template <int N>
__device__ __forceinline__ void cp_wait() {
    asm volatile("cp.async.wait_group %0;" :: "n"(N) : "memory");
}
// fp16 inputs, fp32 accumulate
__device__ __forceinline__ void mma16(float& d0, float& d1, float& d2, float& d3,
                                      uint32_t a0, uint32_t a1, uint32_t a2, uint32_t a3,
                                      uint32_t b0, uint32_t b1) {
    asm volatile(
        "mma.sync.aligned.m16n8k16.row.col.f32.f16.f16.f32 "
        "{%0,%1,%2,%3}, {%4,%5,%6,%7}, {%8,%9}, {%0,%1,%2,%3};"
        : "+f"(d0), "+f"(d1), "+f"(d2), "+f"(d3)
        : "r"(a0), "r"(a1), "r"(a2), "r"(a3), "r"(b0), "r"(b1));
}

// SMEM layout (bytes), 3-stage ring, BK=32 chunks (stride 40 halfs = 80B)
constexpr int GOFF_B  = 0;                        // 64 rows x 6 ints = 1536
constexpr int AOFF_B  = 1536;
constexpr int A_BUF_B = BM * 40 * 2;              // 5120
constexpr int BOFF_B  = AOFF_B + 3 * A_BUF_B;     // 16896
constexpr int B_BUF_B = 256 * 40 * 2;             // 20480
constexpr int SMEM_BYTES = BOFF_B + 3 * B_BUF_B;  // 78336 (2 CTAs/SM: 156KB)

// ---------------------------------------------------------------------------
// Fused gather + fp16 HMMA GEMM. 256 threads, 8 warps as 2(M) x 4(N);
// warp tile 32x64; 2 CTAs/SM. BK=32: 2 k-steps per barrier interval.
// MODE 0: C2h <- raw fp16, Ch <- relu fp16     (init; no gather)
// MODE 1: Ch <- relu(binput + raw) fp16        (rounds; all chunks gathered)
// MODE 2: Ch <- relu(raw + b_o[n]) fp16        (readout; chunks <8 gathered)
// ---------------------------------------------------------------------------
template <int MODE, int KT>
__global__ void __launch_bounds__(256, 2)
gemm_fused(const __half* __restrict__ msg,
           const int* __restrict__ graph,
           const __half* __restrict__ Apad, int ldah,
           const __half* __restrict__ Bt, int ldbh,
           const void* __restrict__ extra,
           __half* __restrict__ Ch,
           __half* __restrict__ C2h, int M) {
    extern __shared__ char smc[];
    int* sgidx = (int*)(smc + GOFF_B);
    const uint32_t sbase = smem_u32(smc);
    const int tid  = threadIdx.x;
    const int wid  = tid >> 5;
    const int lane = tid & 31;
    const int mBase = blockIdx.x * BM;
    const int warpM = (wid >> 2) * 32;   // 0 or 32
    const int warpN = (wid & 3) * 64;    // 0,64,128,192

    constexpr int FEAT0 = (MODE == 2) ? 8 : 0;   // 256/32 = 8 gathered chunks
    auto gathered = [](int s) { return MODE == 1 || (MODE == 2 && s < 8); };

    const int grow = tid >> 2;   // 0..63 (gather row)
    const int gc   = tid & 3;    // 8B slot; covers bytes gc*8 and 32+gc*8

    if (MODE != 0) {
        for (int i = tid; i < BM * MAX_NB; i += 256) {
            int gi = mBase * MAX_NB + i;
            sgidx[i] = (gi < M * MAX_NB) ? graph[gi] : 0;
        }
        __syncthreads();
    }
    const char* msgc = (const char*)msg;

    // direct gather: 12 independent 8B loads (6 neighbors x 2 halves of 64B chunk)
    auto store_gather = [&](int s) {
        uint2 va[6], vb[6];
#pragma unroll
        for (int j = 0; j < 6; ++j) {
            uint32_t idx = (uint32_t)sgidx[grow * 6 + j];
            const char* base = msgc + (size_t)idx * (HIDDEN * 2) + s * (BK * 2);
            va[j] = __ldg((const uint2*)(base + gc * 8));
            vb[j] = __ldg((const uint2*)(base + 32 + gc * 8));
        }
        float a0 = 0.f, a1 = 0.f, a2 = 0.f, a3 = 0.f;
        float b0 = 0.f, b1 = 0.f, b2 = 0.f, b3 = 0.f;
#pragma unroll
        for (int j = 0; j < 6; ++j) {
            float2 lo = __half22float2(*(const __half2*)&va[j].x);
            float2 hi = __half22float2(*(const __half2*)&va[j].y);
            a0 += lo.x; a1 += lo.y; a2 += hi.x; a3 += hi.y;
            lo = __half22float2(*(const __half2*)&vb[j].x);
            hi = __half22float2(*(const __half2*)&vb[j].y);
            b0 += lo.x; b1 += lo.y; b2 += hi.x; b3 += hi.y;
        }
        uint2 r;
        char* dst = smc + AOFF_B + (s % 3) * A_BUF_B + grow * 80;
        *(__half2*)&r.x = __floats2half2_rn(a0, a1);
        *(__half2*)&r.y = __floats2half2_rn(a2, a3);
        *(uint2*)(dst + gc * 8) = r;
        *(__half2*)&r.x = __floats2half2_rn(b0, b1);
        *(__half2*)&r.y = __floats2half2_rn(b2, b3);
        *(uint2*)(dst + 32 + gc * 8) = r;
    };
    auto cpA = [&](int s) {
        int row = tid >> 2, h = tid & 3;   // 64 rows x 4 x 16B = 4KB
        int gm = mBase + row;
        const void* src = Apad + (size_t)gm * ldah + (s - FEAT0) * BK + h * 8;
        uint32_t dst = sbase + AOFF_B + (s % 3) * A_BUF_B + (row * 40 + h * 8) * 2;
        cp16(dst, src, (gm < M) ? 16u : 0u);
    };
    auto cpB = [&](int s) {
#pragma unroll
        for (int i = 0; i < 4; ++i) {
            int e = tid + i * 256;
            int row = e >> 2, h = e & 3;   // 256 rows x 4 x 16B = 16KB
            const void* src = Bt + (size_t)row * ldbh + s * BK + h * 8;
            uint32_t dst = sbase + BOFF_B + (s % 3) * B_BUF_B + (row * 40 + h * 8) * 2;
            cp16(dst, src, 16u);
        }
    };

    // --- prologue: chunks 0 and 1 staged ---
    if (gathered(0)) store_gather(0); else cpA(0);
    cpB(0); cp_commit();
    if (KT > 1) {
        if (gathered(1)) store_gather(1); else cpA(1);
        cpB(1); cp_commit();
    }
    cp_wait<1>();
    __syncthreads();

    float acc[2][8][4];
#pragma unroll
    for (int a = 0; a < 2; ++a)
#pragma unroll
        for (int b = 0; b < 8; ++b)
#pragma unroll
            for (int c = 0; c < 4; ++c) acc[a][b][c] = 0.0f;

#pragma unroll 1
    for (int s = 0; s < KT; ++s) {
        const __half* bA = (const __half*)(smc + AOFF_B + (s % 3) * A_BUF_B);
        const __half* bB = (const __half*)(smc + BOFF_B + (s % 3) * B_BUF_B);

#pragma unroll
        for (int ks = 0; ks < 2; ++ks) {
            const int k0 = ks * 16 + (lane & 3) * 2;
            uint32_t afr[2][4];
#pragma unroll
            for (int mt = 0; mt < 2; ++mt) {
                const int r0 = warpM + mt * 16 + (lane >> 2);
                const int r1 = r0 + 8;
                afr[mt][0] = *(const uint32_t*)&bA[r0 * 40 + k0];
                afr[mt][1] = *(const uint32_t*)&bA[r1 * 40 + k0];
                afr[mt][2] = *(const uint32_t*)&bA[r0 * 40 + k0 + 8];
                afr[mt][3] = *(const uint32_t*)&bA[r1 * 40 + k0 + 8];
            }
#pragma unroll
            for (int nt = 0; nt < 8; ++nt) {
                const int nn = warpN + nt * 8 + (lane >> 2);
                uint32_t b0 = *(const uint32_t*)&bB[nn * 40 + k0];
                uint32_t b1 = *(const uint32_t*)&bB[nn * 40 + k0 + 8];
#pragma unroll
                for (int mt = 0; mt < 2; ++mt)
                    mma16(acc[mt][nt][0], acc[mt][nt][1], acc[mt][nt][2], acc[mt][nt][3],
                          afr[mt][0], afr[mt][1], afr[mt][2], afr[mt][3], b0, b1);
            }
        }

        // stage s+1 gather (buf (s+1)%3) and s+2 cp.async (buf (s+2)%3)
        if (s + 1 < KT && gathered(s + 1)) store_gather(s + 1);
        if (s + 2 < KT) {
            if (!gathered(s + 2)) cpA(s + 2);
            cpB(s + 2);
        }
        cp_commit();
        cp_wait<1>();
        __syncthreads();
    }

    // --- epilogue ---
#pragma unroll
    for (int mt = 0; mt < 2; ++mt) {
#pragma unroll
        for (int rg = 0; rg < 2; ++rg) {
            const int r = mBase + warpM + mt * 16 + (lane >> 2) + rg * 8;
            if (r < M) {
#pragma unroll
                for (int nt = 0; nt < 8; ++nt) {
                    const int col = warpN + nt * 8 + (lane & 3) * 2;
                    const size_t off = (size_t)r * HIDDEN + col;
                    float v0 = acc[mt][nt][rg * 2 + 0];
                    float v1 = acc[mt][nt][rg * 2 + 1];
                    if (MODE == 1) {
                        float2 ef = __half22float2(*(const __half2*)((const __half*)extra + off));
                        v0 += ef.x; v1 += ef.y;
                    }
                    if (MODE == 2) {
                        const float* bo = (const float*)extra;
                        v0 += __ldg(bo + col);
                        v1 += __ldg(bo + col + 1);
                    }
                    if (MODE == 0)
                        *(__half2*)(C2h + off) = __floats2half2_rn(v0, v1);
                    v0 = fmaxf(v0, 0.0f); v1 = fmaxf(v1, 0.0f);
                    *(__half2*)(Ch + off) = __floats2half2_rn(v0, v1);
                }
            }
        }
    }
}

// ---------------------------------------------------------------------------
// Producers
// ---------------------------------------------------------------------------
__global__ void pad_fb_k(const float* __restrict__ in, __half* __restrict__ out) {
    size_t i = (size_t)blockIdx.x * blockDim.x + threadIdx.x;
    if (i >= (size_t)N_BONDS * KP0) return;
    int r = (int)(i / KP0), c = (int)(i % KP0);
    out[i] = (c < IN_FDIM) ? __float2half_rn(in[(size_t)r * IN_FDIM + c]) : __half(0.f);
}
__global__ void cv_wi_k(const float* __restrict__ W, __half* __restrict__ out) {
    int i = blockIdx.x * blockDim.x + threadIdx.x;
    if (i >= HIDDEN * KP0) return;
    int n = i / KP0, k = i % KP0;
    out[i] = (k < IN_FDIM) ? __float2half_rn(W[(size_t)n * IN_FDIM + k]) : __half(0.f);
}
__global__ void cv_wh_k(const float* __restrict__ W, __half* __restrict__ out) {
    int i = blockIdx.x * blockDim.x + threadIdx.x;
    if (i >= HIDDEN * KP1) return;
    out[i] = __float2half_rn(W[i]);
}
__global__ void cv_wo_k(const float* __restrict__ W, __half* __restrict__ out) {
    int i = blockIdx.x * blockDim.x + threadIdx.x;
    if (i >= HIDDEN * KP2) return;
    int n = i / KP2, k = i % KP2;
    float v = 0.0f;
    if (k < 256) v = W[(size_t)n * OUT_FDIM + ATOM_FDIM + k];
    else if (k < OUT_FDIM) v = W[(size_t)n * OUT_FDIM + (k - 256)];
    out[i] = __float2half_rn(v);
}
__global__ void pad_afeat_k(const float* __restrict__ fatoms, __half* __restrict__ afeat) {
    int i = blockIdx.x * blockDim.x + threadIdx.x;
    if (i >= N_ATOMS * 64) return;
    int r = i / 64, c = i % 64;
    afeat[i] = (c < ATOM_FDIM) ? __float2half_rn(fatoms[(size_t)r * ATOM_FDIM + c]) : __half(0.f);
}

__global__ void pool_k(const __half* __restrict__ atomh, float* __restrict__ out) {
    const int mol = blockIdx.x;
    const int n   = threadIdx.x;
    const __half* base = atomh + (size_t)mol * APM * HIDDEN;
    float s = 0.0f;
#pragma unroll
    for (int i = 0; i < APM; ++i) s += __half2float(base[(size_t)i * HIDDEN + n]);
    out[(size_t)mol * HIDDEN + n] = s * (1.0f / (float)APM);
}

// ---------------------------------------------------------------------------
extern "C" void kernel_launch(void* const* d_in, const int* in_sizes, int n_in,
                              void* d_out, int out_size) {
    const float* fatoms = (const float*)d_in[0];
    const float* fbonds = (const float*)d_in[1];
    const int*   agraph = (const int*)  d_in[2];
    const int*   bgraph = (const int*)  d_in[3];
    const float* W_i = (const float*)d_in[5];
    const float* W_h = (const float*)d_in[6];
    const float* W_o = (const float*)d_in[7];
    const float* b_o = (const float*)d_in[8];
    float* out = (float*)d_out;

    __half *binput, *msg0, *msg1, *atomh, *fbpad, *afeat, *Wi, *Wh, *Wo;
    cudaGetSymbolAddress((void**)&binput, g_binput);
    cudaGetSymbolAddress((void**)&msg0,   g_msg0);
    cudaGetSymbolAddress((void**)&msg1,   g_msg1);
    cudaGetSymbolAddress((void**)&atomh,  g_atomh);
    cudaGetSymbolAddress((void**)&fbpad,  g_fbpad);
    cudaGetSymbolAddress((void**)&afeat,  g_afeat);
    cudaGetSymbolAddress((void**)&Wi,     g_Wi);
    cudaGetSymbolAddress((void**)&Wh,     g_Wh);
    cudaGetSymbolAddress((void**)&Wo,     g_Wo);

    cudaFuncSetAttribute(gemm_fused<0, KP0 / BK>, cudaFuncAttributeMaxDynamicSharedMemorySize, SMEM_BYTES);
    cudaFuncSetAttribute(gemm_fused<1, KP1 / BK>, cudaFuncAttributeMaxDynamicSharedMemorySize, SMEM_BYTES);
    cudaFuncSetAttribute(gemm_fused<2, KP2 / BK>, cudaFuncAttributeMaxDynamicSharedMemorySize, SMEM_BYTES);

    {
        size_t n = (size_t)N_BONDS * KP0;
        pad_fb_k<<<(unsigned)((n + 255) / 256), 256>>>(fbonds, fbpad);
        cv_wi_k<<<(HIDDEN * KP0 + 255) / 256, 256>>>(W_i, Wi);
        cv_wh_k<<<(HIDDEN * KP1 + 255) / 256, 256>>>(W_h, Wh);
        cv_wo_k<<<(HIDDEN * KP2 + 255) / 256, 256>>>(W_o, Wo);
        pad_afeat_k<<<(N_ATOMS * 64 + 255) / 256, 256>>>(fatoms, afeat);
    }

    const int tilesB = (N_BONDS + BM - 1) / BM;
    const int tilesA = (N_ATOMS + BM - 1) / BM;

    // init: binput(raw fp16) + msg0 = relu fp16
    gemm_fused<0, KP0 / BK><<<tilesB, 256, SMEM_BYTES>>>(
        nullptr, nullptr, fbpad, KP0, Wi, KP0,
        nullptr, msg0, binput, N_BONDS);

    // 5 message-passing rounds (gather fused)
    __half* cur = msg0;
    __half* nxt = msg1;
    for (int r = 0; r < 5; ++r) {
        gemm_fused<1, KP1 / BK><<<tilesB, 256, SMEM_BYTES>>>(
            cur, bgraph, nullptr, 0, Wh, KP1,
            binput, nxt, nullptr, N_BONDS);
        __half* t = cur; cur = nxt; nxt = t;
    }

    // atom readout (fp16 out)
    gemm_fused<2, KP2 / BK><<<tilesA, 256, SMEM_BYTES>>>(
        cur, agraph, afeat, 64, Wo, KP2,
        b_o, atomh, nullptr, N_ATOMS);

    // mean pool (fp32 accumulate)
    pool_k<<<N_MOLS, 256>>>(atomh, out);
}

// round 14
// speedup vs baseline: 1.9620x; 1.1271x over previous
#include <cuda_runtime.h>
#include <cuda_fp16.h>
#include <cstdint>
#include <cstddef>

// ---------------------------------------------------------------------------
// Problem constants
// ---------------------------------------------------------------------------
constexpr int N_ATOMS  = 100000;
constexpr int N_BONDS  = 200001;
constexpr int ATOM_FDIM = 39;
constexpr int IN_FDIM   = 50;
constexpr int OUT_FDIM  = 295;
constexpr int MAX_NB    = 6;
constexpr int HIDDEN    = 256;
constexpr int N_MOLS    = 2000;
constexpr int APM       = 50;

constexpr int KP0 = 64;    // init K (50 -> 64)
constexpr int KP1 = 256;   // rounds K
constexpr int KP2 = 320;   // readout K: [nei(256) | fatoms(39) | pad]
constexpr int BK  = 64;    // four m16n8k16 steps per chunk (4 barriers/round)
constexpr int BM  = 64;    // M tile (256 threads, 2 CTAs/SM)

// ---------------------------------------------------------------------------
// Scratch (fp16 everywhere except final pool output)
// ---------------------------------------------------------------------------
__device__ __align__(16) __half g_binput[(size_t)N_BONDS * HIDDEN];
__device__ __align__(16) __half g_msg0  [(size_t)N_BONDS * HIDDEN];
__device__ __align__(16) __half g_msg1  [(size_t)N_BONDS * HIDDEN];
__device__ __align__(16) __half g_atomh [(size_t)N_ATOMS * HIDDEN];
__device__ __align__(16) __half g_fbpad [(size_t)N_BONDS * KP0];
__device__ __align__(16) __half g_afeat [(size_t)N_ATOMS * 64];
__device__ __align__(16) __half g_Wi    [(size_t)HIDDEN * KP0];   // [n][k]
__device__ __align__(16) __half g_Wh    [(size_t)HIDDEN * KP1];   // [n][k]
__device__ __align__(16) __half g_Wo    [(size_t)HIDDEN * KP2];   // [n][k], cols reordered

// ---------------------------------------------------------------------------
// Helpers
// ---------------------------------------------------------------------------
__device__ __forceinline__ uint32_t smem_u32(const void* p) {
    uint32_t a;
    asm("{ .reg .u64 t; cvta.to.shared.u64 t, %1; cvt.u32.u64 %0, t; }" : "=r"(a) : "l"(p));
    return a;
}
__device__ __forceinline__ void cp16(uint32_t dst, const void* src, uint32_t sz) {
    asm volatile("cp.async.ca.shared.global [%0], [%1], 16, %2;" :: "r"(dst), "l"(src), "r"(sz) : "memory");
}
__device__ __forceinline__ void cp_commit() {
    asm volatile("cp.async.commit_group;" ::: "memory");
}
template <int N>
__device__ __forceinline__ void cp_wait() {
    asm volatile("cp.async.wait_group %0;" :: "n"(N) : "memory");
}
// fp16 inputs, fp32 accumulate
__device__ __forceinline__ void mma16(float& d0, float& d1, float& d2, float& d3,
                                      uint32_t a0, uint32_t a1, uint32_t a2, uint32_t a3,
                                      uint32_t b0, uint32_t b1) {
    asm volatile(
        "mma.sync.aligned.m16n8k16.row.col.f32.f16.f16.f32 "
        "{%0,%1,%2,%3}, {%4,%5,%6,%7}, {%8,%9}, {%0,%1,%2,%3};"
        : "+f"(d0), "+f"(d1), "+f"(d2), "+f"(d3)
        : "r"(a0), "r"(a1), "r"(a2), "r"(a3), "r"(b0), "r"(b1));
}

// SMEM layout (bytes), TWO-stage rings (lookahead-1 is race-free), BK=64
// chunks, tile row stride 72 halfs (64 + 8 pad) = 144B (conflict-free frags).
constexpr int GOFF_B  = 0;                        // 64 rows x 6 ints = 1536
constexpr int AOFF_B  = 1536;
constexpr int A_BUF_B = BM * 72 * 2;              // 9216
constexpr int BOFF_B  = AOFF_B + 2 * A_BUF_B;     // 19968
constexpr int B_BUF_B = 256 * 72 * 2;             // 36864
constexpr int SMEM_BYTES = BOFF_B + 2 * B_BUF_B;  // 93696 (2 CTAs/SM: 187KB)

// ---------------------------------------------------------------------------
// Fused gather + fp16 HMMA GEMM. 256 threads, 8 warps as 2(M) x 4(N);
// warp tile 32x64; 2 CTAs/SM. BK=64: 4 k-steps per barrier interval.
// Gather is phased: phase0 (6x16B) issued BEFORE the chunk's MMA (covered),
// phase1 issued after (covered by cp-wait + cross-warp).
// MODE 0: C2h <- raw fp16, Ch <- relu fp16     (init; no gather)
// MODE 1: Ch <- relu(binput + raw) fp16        (rounds; all chunks gathered)
// MODE 2: Ch <- relu(raw + b_o[n]) fp16        (readout; chunks <4 gathered)
// ---------------------------------------------------------------------------
template <int MODE, int KT>
__global__ void __launch_bounds__(256, 2)
gemm_fused(const __half* __restrict__ msg,
           const int* __restrict__ graph,
           const __half* __restrict__ Apad, int ldah,
           const __half* __restrict__ Bt, int ldbh,
           const void* __restrict__ extra,
           __half* __restrict__ Ch,
           __half* __restrict__ C2h, int M) {
    extern __shared__ char smc[];
    int* sgidx = (int*)(smc + GOFF_B);
    const uint32_t sbase = smem_u32(smc);
    const int tid  = threadIdx.x;
    const int wid  = tid >> 5;
    const int lane = tid & 31;
    const int mBase = blockIdx.x * BM;
    const int warpM = (wid >> 2) * 32;   // 0 or 32
    const int warpN = (wid & 3) * 64;    // 0,64,128,192

    constexpr int FEAT0 = (MODE == 2) ? 4 : 0;   // 256/64 = 4 gathered chunks
    auto gathered = [](int s) { return MODE == 1 || (MODE == 2 && s < 4); };

    const int grow = tid >> 2;   // 0..63 (gather row)
    const int gc   = tid & 3;    // 16B slot within 64B half-chunk

    if (MODE != 0) {
        for (int i = tid; i < BM * MAX_NB; i += 256) {
            int gi = mBase * MAX_NB + i;
            sgidx[i] = (gi < M * MAX_NB) ? graph[gi] : 0;
        }
        __syncthreads();
    }
    const char* msgc = (const char*)msg;

    // phase ph covers bytes [ph*64 + gc*16, +16) of the 128B chunk
    auto issue_phase = [&](int s, int ph, uint4* v) {
#pragma unroll
        for (int j = 0; j < 6; ++j) {
            uint32_t idx = (uint32_t)sgidx[grow * 6 + j];
            v[j] = __ldg((const uint4*)(msgc + (size_t)idx * (HIDDEN * 2)
                                        + s * (BK * 2) + ph * 64 + gc * 16));
        }
    };
    auto sum_store = [&](int s, int ph, const uint4* v) {
        float f[8];
#pragma unroll
        for (int t = 0; t < 8; ++t) f[t] = 0.0f;
#pragma unroll
        for (int j = 0; j < 6; ++j) {
            const __half2* h2 = (const __half2*)&v[j];
#pragma unroll
            for (int q = 0; q < 4; ++q) {
                float2 e = __half22float2(h2[q]);
                f[q * 2] += e.x; f[q * 2 + 1] += e.y;
            }
        }
        uint4 r;
        __half2* rh = (__half2*)&r;
#pragma unroll
        for (int q = 0; q < 4; ++q) rh[q] = __floats2half2_rn(f[q * 2], f[q * 2 + 1]);
        *(uint4*)(smc + AOFF_B + (s & 1) * A_BUF_B + grow * 144 + ph * 64 + gc * 16) = r;
    };
    auto cpA = [&](int s) {
#pragma unroll
        for (int i = 0; i < 2; ++i) {
            int e = tid + i * 256;
            int row = e >> 3, h = e & 7;    // 64 rows x 8 x 16B
            int gm = mBase + row;
            const void* src = Apad + (size_t)gm * ldah + (s - FEAT0) * BK + h * 8;
            uint32_t dst = sbase + AOFF_B + (s & 1) * A_BUF_B + (row * 72 + h * 8) * 2;
            cp16(dst, src, (gm < M) ? 16u : 0u);
        }
    };
    auto cpB = [&](int s) {
#pragma unroll
        for (int i = 0; i < 8; ++i) {
            int e = tid + i * 256;
            int row = e >> 3, h = e & 7;    // 256 rows x 8 x 16B
            const void* src = Bt + (size_t)row * ldbh + s * BK + h * 8;
            uint32_t dst = sbase + BOFF_B + (s & 1) * B_BUF_B + (row * 72 + h * 8) * 2;
            cp16(dst, src, 16u);
        }
    };

    // --- prologue: stage chunk 0 ---
    if (gathered(0)) {
        uint4 v[6];
        issue_phase(0, 0, v); sum_store(0, 0, v);
        issue_phase(0, 1, v); sum_store(0, 1, v);
    } else cpA(0);
    cpB(0); cp_commit();
    cp_wait<0>();
    __syncthreads();

    float acc[2][8][4];
#pragma unroll
    for (int a = 0; a < 2; ++a)
#pragma unroll
        for (int b = 0; b < 8; ++b)
#pragma unroll
            for (int c = 0; c < 4; ++c) acc[a][b][c] = 0.0f;

    uint4 vh[6];   // phase-0 gather prefetch for chunk s+1

#pragma unroll 1
    for (int s = 0; s < KT; ++s) {
        // stage s+1: gather phase-0 loads + cp.async (into the OTHER buffer)
        if (s + 1 < KT) {
            if (gathered(s + 1)) issue_phase(s + 1, 0, vh);
            else cpA(s + 1);
            cpB(s + 1);
        }
        cp_commit();

        const __half* bA = (const __half*)(smc + AOFF_B + (s & 1) * A_BUF_B);
        const __half* bB = (const __half*)(smc + BOFF_B + (s & 1) * B_BUF_B);

#pragma unroll
        for (int ks = 0; ks < 4; ++ks) {
            const int k0 = ks * 16 + (lane & 3) * 2;
            uint32_t afr[2][4];
#pragma unroll
            for (int mt = 0; mt < 2; ++mt) {
                const int r0 = warpM + mt * 16 + (lane >> 2);
                const int r1 = r0 + 8;
                afr[mt][0] = *(const uint32_t*)&bA[r0 * 72 + k0];
                afr[mt][1] = *(const uint32_t*)&bA[r1 * 72 + k0];
                afr[mt][2] = *(const uint32_t*)&bA[r0 * 72 + k0 + 8];
                afr[mt][3] = *(const uint32_t*)&bA[r1 * 72 + k0 + 8];
            }
#pragma unroll
            for (int nt = 0; nt < 8; ++nt) {
                const int nn = warpN + nt * 8 + (lane >> 2);
                uint32_t b0 = *(const uint32_t*)&bB[nn * 72 + k0];
                uint32_t b1 = *(const uint32_t*)&bB[nn * 72 + k0 + 8];
#pragma unroll
                for (int mt = 0; mt < 2; ++mt)
                    mma16(acc[mt][nt][0], acc[mt][nt][1], acc[mt][nt][2], acc[mt][nt][3],
                          afr[mt][0], afr[mt][1], afr[mt][2], afr[mt][3], b0, b1);
            }
        }

        // finish staging s+1's gather: store phase-0, then phase-1
        if (s + 1 < KT && gathered(s + 1)) {
            sum_store(s + 1, 0, vh);
            issue_phase(s + 1, 1, vh);
            sum_store(s + 1, 1, vh);
        }
        cp_wait<0>();
        __syncthreads();
    }

    // --- epilogue ---
#pragma unroll
    for (int mt = 0; mt < 2; ++mt) {
#pragma unroll
        for (int rg = 0; rg < 2; ++rg) {
            const int r = mBase + warpM + mt * 16 + (lane >> 2) + rg * 8;
            if (r < M) {
#pragma unroll
                for (int nt = 0; nt < 8; ++nt) {
                    const int col = warpN + nt * 8 + (lane & 3) * 2;
                    const size_t off = (size_t)r * HIDDEN + col;
                    float v0 = acc[mt][nt][rg * 2 + 0];
                    float v1 = acc[mt][nt][rg * 2 + 1];
                    if (MODE == 1) {
                        float2 ef = __half22float2(*(const __half2*)((const __half*)extra + off));
                        v0 += ef.x; v1 += ef.y;
                    }
                    if (MODE == 2) {
                        const float* bo = (const float*)extra;
                        v0 += __ldg(bo + col);
                        v1 += __ldg(bo + col + 1);
                    }
                    if (MODE == 0)
                        *(__half2*)(C2h + off) = __floats2half2_rn(v0, v1);
                    v0 = fmaxf(v0, 0.0f); v1 = fmaxf(v1, 0.0f);
                    *(__half2*)(Ch + off) = __floats2half2_rn(v0, v1);
                }
            }
        }
    }
}

// ---------------------------------------------------------------------------
// Producers
// ---------------------------------------------------------------------------
__global__ void pad_fb_k(const float* __restrict__ in, __half* __restrict__ out) {
    size_t i = (size_t)blockIdx.x * blockDim.x + threadIdx.x;
    if (i >= (size_t)N_BONDS * KP0) return;
    int r = (int)(i / KP0), c = (int)(i % KP0);
    out[i] = (c < IN_FDIM) ? __float2half_rn(in[(size_t)r * IN_FDIM + c]) : __half(0.f);
}
__global__ void cv_wi_k(const float* __restrict__ W, __half* __restrict__ out) {
    int i = blockIdx.x * blockDim.x + threadIdx.x;
    if (i >= HIDDEN * KP0) return;
    int n = i / KP0, k = i % KP0;
    out[i] = (k < IN_FDIM) ? __float2half_rn(W[(size_t)n * IN_FDIM + k]) : __half(0.f);
}
__global__ void cv_wh_k(const float* __restrict__ W, __half* __restrict__ out) {
    int i = blockIdx.x * blockDim.x + threadIdx.x;
    if (i >= HIDDEN * KP1) return;
    out[i] = __float2half_rn(W[i]);
}
__global__ void cv_wo_k(const float* __restrict__ W, __half* __restrict__ out) {
    int i = blockIdx.x * blockDim.x + threadIdx.x;
    if (i >= HIDDEN * KP2) return;
    int n = i / KP2, k = i % KP2;
    float v = 0.0f;
    if (k < 256) v = W[(size_t)n * OUT_FDIM + ATOM_FDIM + k];
    else if (k < OUT_FDIM) v = W[(size_t)n * OUT_FDIM + (k - 256)];
    out[i] = __float2half_rn(v);
}
__global__ void pad_afeat_k(const float* __restrict__ fatoms, __half* __restrict__ afeat) {
    int i = blockIdx.x * blockDim.x + threadIdx.x;
    if (i >= N_ATOMS * 64) return;
    int r = i / 64, c = i % 64;
    afeat[i] = (c < ATOM_FDIM) ? __float2half_rn(fatoms[(size_t)r * ATOM_FDIM + c]) : __half(0.f);
}

__global__ void pool_k(const __half* __restrict__ atomh, float* __restrict__ out) {
    const int mol = blockIdx.x;
    const int n   = threadIdx.x;
    const __half* base = atomh + (size_t)mol * APM * HIDDEN;
    float s = 0.0f;
#pragma unroll
    for (int i = 0; i < APM; ++i) s += __half2float(base[(size_t)i * HIDDEN + n]);
    out[(size_t)mol * HIDDEN + n] = s * (1.0f / (float)APM);
}

// ---------------------------------------------------------------------------
extern "C" void kernel_launch(void* const* d_in, const int* in_sizes, int n_in,
                              void* d_out, int out_size) {
    const float* fatoms = (const float*)d_in[0];
    const float* fbonds = (const float*)d_in[1];
    const int*   agraph = (const int*)  d_in[2];
    const int*   bgraph = (const int*)  d_in[3];
    const float* W_i = (const float*)d_in[5];
    const float* W_h = (const float*)d_in[6];
    const float* W_o = (const float*)d_in[7];
    const float* b_o = (const float*)d_in[8];
    float* out = (float*)d_out;

    __half *binput, *msg0, *msg1, *atomh, *fbpad, *afeat, *Wi, *Wh, *Wo;
    cudaGetSymbolAddress((void**)&binput, g_binput);
    cudaGetSymbolAddress((void**)&msg0,   g_msg0);
    cudaGetSymbolAddress((void**)&msg1,   g_msg1);
    cudaGetSymbolAddress((void**)&atomh,  g_atomh);
    cudaGetSymbolAddress((void**)&fbpad,  g_fbpad);
    cudaGetSymbolAddress((void**)&afeat,  g_afeat);
    cudaGetSymbolAddress((void**)&Wi,     g_Wi);
    cudaGetSymbolAddress((void**)&Wh,     g_Wh);
    cudaGetSymbolAddress((void**)&Wo,     g_Wo);

    cudaFuncSetAttribute(gemm_fused<0, KP0 / BK>, cudaFuncAttributeMaxDynamicSharedMemorySize, SMEM_BYTES);
    cudaFuncSetAttribute(gemm_fused<1, KP1 / BK>, cudaFuncAttributeMaxDynamicSharedMemorySize, SMEM_BYTES);
    cudaFuncSetAttribute(gemm_fused<2, KP2 / BK>, cudaFuncAttributeMaxDynamicSharedMemorySize, SMEM_BYTES);

    {
        size_t n = (size_t)N_BONDS * KP0;
        pad_fb_k<<<(unsigned)((n + 255) / 256), 256>>>(fbonds, fbpad);
        cv_wi_k<<<(HIDDEN * KP0 + 255) / 256, 256>>>(W_i, Wi);
        cv_wh_k<<<(HIDDEN * KP1 + 255) / 256, 256>>>(W_h, Wh);
        cv_wo_k<<<(HIDDEN * KP2 + 255) / 256, 256>>>(W_o, Wo);
        pad_afeat_k<<<(N_ATOMS * 64 + 255) / 256, 256>>>(fatoms, afeat);
    }

    const int tilesB = (N_BONDS + BM - 1) / BM;
    const int tilesA = (N_ATOMS + BM - 1) / BM;

    // init: binput(raw fp16) + msg0 = relu fp16 (KT=1)
    gemm_fused<0, KP0 / BK><<<tilesB, 256, SMEM_BYTES>>>(
        nullptr, nullptr, fbpad, KP0, Wi, KP0,
        nullptr, msg0, binput, N_BONDS);

    // 5 message-passing rounds (gather fused, KT=4 -> 4 barriers/round)
    __half* cur = msg0;
    __half* nxt = msg1;
    for (int r = 0; r < 5; ++r) {
        gemm_fused<1, KP1 / BK><<<tilesB, 256, SMEM_BYTES>>>(
            cur, bgraph, nullptr, 0, Wh, KP1,
            binput, nxt, nullptr, N_BONDS);
        __half* t = cur; cur = nxt; nxt = t;
    }

    // atom readout (fp16 out, KT=5: 4 gathered + 1 feature chunk)
    gemm_fused<2, KP2 / BK><<<tilesA, 256, SMEM_BYTES>>>(
        cur, agraph, afeat, 64, Wo, KP2,
        b_o, atomh, nullptr, N_ATOMS);

    // mean pool (fp32 accumulate)
    pool_k<<<N_MOLS, 256>>>(atomh, out);
}